// round 5
// baseline (speedup 1.0000x reference)
#include <cuda_runtime.h>
#include <math.h>

// Problem constants (fixed shapes)
#define N_PIX   131072          // 32 * 64 * 64
#define K_CODE  1024
#define D_DIM   64
#define N_ELEM  8388608         // 32*64*64*64 (full NCHW tensor)

// Output layout offsets (flattened tuple, float32) — total 8651778
#define QUANT_OFF 0
#define LOSS_OFF  8388608
#define PERP_OFF  8388609
#define IDX_OFF   8388610
#define NCS_OFF   8519682
#define NEMA_OFF  8520706
#define NEMB_OFF  8586242

// Scratch (device globals; no allocation allowed)
__device__ int   g_idx[N_PIX];
__device__ float g_embT[D_DIM * K_CODE];   // embT[d][k]
__device__ float g_esq[K_CODE];
__device__ float g_counts[K_CODE];
__device__ float g_dw[K_CODE * D_DIM];
__device__ float g_scl[K_CODE];
__device__ float g_loss;

typedef unsigned long long u64;

// packed f32x2 helpers (sm_103a; FFMA2 only reachable via PTX)
__device__ __forceinline__ u64 bcast2(float x) {
    u64 r;
    unsigned xi = __float_as_uint(x);
    asm("mov.b64 %0, {%1, %1};" : "=l"(r) : "r"(xi));
    return r;
}
__device__ __forceinline__ u64 pack2(float lo, float hi) {
    u64 r;
    asm("mov.b64 %0, {%1, %2};" : "=l"(r) : "r"(__float_as_uint(lo)), "r"(__float_as_uint(hi)));
    return r;
}
__device__ __forceinline__ void ffma2(u64& d, u64 a, u64 b) {
    asm("fma.rn.f32x2 %0, %1, %2, %0;" : "+l"(d) : "l"(a), "l"(b));
}
__device__ __forceinline__ void unpack2(float& lo, float& hi, u64 v) {
    unsigned l, h;
    asm("mov.b64 {%0, %1}, %2;" : "=r"(l), "=r"(h) : "l"(v));
    lo = __uint_as_float(l); hi = __uint_as_float(h);
}

// ---------------------------------------------------------------------------
// Kernel 1: transpose embed -> embT, ||e_k||^2, zero accumulators
// ---------------------------------------------------------------------------
__global__ void prep_kernel(const float* __restrict__ embed) {
    int k = blockIdx.x;
    int t = threadIdx.x;
    float v = embed[k * 64 + t];
    g_embT[t * 1024 + k] = v;
    g_dw[k * 64 + t] = 0.0f;
    float s = v * v;
    #pragma unroll
    for (int o = 16; o; o >>= 1) s += __shfl_down_sync(0xffffffffu, s, o);
    __shared__ float sm[2];
    if ((t & 31) == 0) sm[t >> 5] = s;
    __syncthreads();
    if (t == 0) {
        g_esq[k] = sm[0] + sm[1];
        g_counts[k] = 0.0f;
        if (k == 0) g_loss = 0.0f;
    }
}

// ---------------------------------------------------------------------------
// Kernel 2 (primary): argmin GEMM with packed f32x2 FMA.
// Block = 256 pixels, 64-code chunks in smem, 256 threads, 8x8 tile.
// acc packed along codes: acc2[pixel][codepair]. B pairs come free from
// float4 smem loads; A needs one mov.b64 broadcast per pixel per d.
// Tracks s = x.e - 0.5*||e||^2 ; argmin dist == argmax s. Bit-identical to fmaf.
// ---------------------------------------------------------------------------
#define ARGMIN_SMEM (80 * 1024)
__global__ void __launch_bounds__(256, 2) argmin_dyn(const float* __restrict__ in,
                                                     float* __restrict__ out) {
    extern __shared__ float4 sh4[];
    float4* xs4 = sh4;            // xs[d][p]: d*64 + p/4  (4096 float4, 64KB)
    float4* es4 = sh4 + 4096;     // es[d][k]: d*16 + k/4  (1024 float4, 16KB)
    const ulonglong2* esu2 = (const ulonglong2*)es4;

    const int tid = threadIdx.x;
    const int tx  = tid & 7;      // code group: 8 codes
    const int ty  = tid >> 3;     // pixel group: 8 pixels (0..31)
    const int p0  = blockIdx.x * 256;
    const int bimg = p0 >> 12;
    const int hw0  = p0 & 4095;

    // Load pixel tile: xs[c][p] = in[bimg][c][hw0+p], fully coalesced float4
    const float4* in4 = (const float4*)(in + (size_t)bimg * 262144 + hw0);
    #pragma unroll
    for (int t = 0; t < 16; t++) {
        int i = tid + t * 256;            // 0..4095
        int c = i >> 6, p4 = i & 63;
        xs4[i] = in4[c * 1024 + p4];
    }

    float bestv[8];
    int   besti[8];
    #pragma unroll
    for (int i = 0; i < 8; i++) { bestv[i] = -3.4e38f; besti[i] = 0; }

    const float4* embT4 = (const float4*)g_embT;
    const float4* esq4  = (const float4*)g_esq;

    for (int ck = 0; ck < 16; ck++) {
        __syncthreads();
        #pragma unroll
        for (int t = 0; t < 4; t++) {
            int i = tid + t * 256;        // 0..1023
            int d = i >> 4, k4 = i & 15;
            es4[i] = embT4[d * 256 + ck * 16 + k4];
        }
        __syncthreads();

        // init packed accs with -0.5*||e||^2 per code pair
        float4 e0 = esq4[ck * 16 + tx * 2];
        float4 e1 = esq4[ck * 16 + tx * 2 + 1];
        u64 ei[4];
        ei[0] = pack2(-0.5f * e0.x, -0.5f * e0.y);
        ei[1] = pack2(-0.5f * e0.z, -0.5f * e0.w);
        ei[2] = pack2(-0.5f * e1.x, -0.5f * e1.y);
        ei[3] = pack2(-0.5f * e1.z, -0.5f * e1.w);
        u64 acc2[8][4];
        #pragma unroll
        for (int i = 0; i < 8; i++)
            #pragma unroll
            for (int j = 0; j < 4; j++) acc2[i][j] = ei[j];

        #pragma unroll 4
        for (int d = 0; d < 64; d++) {
            float4 a0 = xs4[d * 64 + ty * 2];
            float4 a1 = xs4[d * 64 + ty * 2 + 1];
            ulonglong2 b0 = esu2[d * 16 + tx * 2];       // codes (0,1),(2,3)
            ulonglong2 b1 = esu2[d * 16 + tx * 2 + 1];   // codes (4,5),(6,7)
            u64 aa[8];
            aa[0] = bcast2(a0.x); aa[1] = bcast2(a0.y);
            aa[2] = bcast2(a0.z); aa[3] = bcast2(a0.w);
            aa[4] = bcast2(a1.x); aa[5] = bcast2(a1.y);
            aa[6] = bcast2(a1.z); aa[7] = bcast2(a1.w);
            #pragma unroll
            for (int i = 0; i < 8; i++) {
                ffma2(acc2[i][0], aa[i], b0.x);
                ffma2(acc2[i][1], aa[i], b0.y);
                ffma2(acc2[i][2], aa[i], b1.x);
                ffma2(acc2[i][3], aa[i], b1.y);
            }
        }

        // running argmax (codes visited in increasing k; strict > keeps lowest)
        #pragma unroll
        for (int j = 0; j < 4; j++) {
            int kg = ck * 64 + tx * 8 + j * 2;
            #pragma unroll
            for (int i = 0; i < 8; i++) {
                float vlo, vhi;
                unpack2(vlo, vhi, acc2[i][j]);
                if (vlo > bestv[i]) { bestv[i] = vlo; besti[i] = kg; }
                if (vhi > bestv[i]) { bestv[i] = vhi; besti[i] = kg + 1; }
            }
        }
    }

    // Reduce across the 8 code-group lanes (consecutive tids, same warp)
    #pragma unroll
    for (int i = 0; i < 8; i++) {
        float v = bestv[i];
        int   ix = besti[i];
        #pragma unroll
        for (int o = 4; o; o >>= 1) {
            float v2 = __shfl_xor_sync(0xffffffffu, v, o);
            int   i2 = __shfl_xor_sync(0xffffffffu, ix, o);
            if (v2 > v || (v2 == v && i2 < ix)) { v = v2; ix = i2; }
        }
        if (tx == 0) {
            int n = p0 + ty * 8 + i;
            g_idx[n] = ix;
            out[IDX_OFF + n] = (float)ix;
        }
    }
}

// ---------------------------------------------------------------------------
// Kernel 2 (fallback): proven 48KB-static scalar version, 128 pixels/block
// ---------------------------------------------------------------------------
__global__ void __launch_bounds__(256) argmin_static(const float* __restrict__ in,
                                                     float* __restrict__ out) {
    __shared__ float4 xs4[2048];
    __shared__ float4 es4[1024];

    const int tid = threadIdx.x;
    const int tx  = tid & 7;
    const int ty  = tid >> 3;
    const int p0  = blockIdx.x * 128;
    const int bimg = p0 >> 12;
    const int hw0  = p0 & 4095;

    const float4* in4 = (const float4*)(in + (size_t)bimg * 262144 + hw0);
    #pragma unroll
    for (int t = 0; t < 8; t++) {
        int i = tid + t * 256;
        int c = i >> 5, p4 = i & 31;
        xs4[i] = in4[c * 1024 + p4];
    }

    float bestv[4];
    int   besti[4];
    #pragma unroll
    for (int i = 0; i < 4; i++) { bestv[i] = -3.4e38f; besti[i] = 0; }

    const float4* embT4 = (const float4*)g_embT;
    const float4* esq4  = (const float4*)g_esq;

    for (int ck = 0; ck < 16; ck++) {
        __syncthreads();
        #pragma unroll
        for (int t = 0; t < 4; t++) {
            int i = tid + t * 256;
            int d = i >> 4, k4 = i & 15;
            es4[i] = embT4[d * 256 + ck * 16 + k4];
        }
        __syncthreads();

        float4 e0 = esq4[ck * 16 + tx * 2];
        float4 e1 = esq4[ck * 16 + tx * 2 + 1];
        float acc[4][8];
        #pragma unroll
        for (int i = 0; i < 4; i++) {
            acc[i][0] = -0.5f * e0.x; acc[i][1] = -0.5f * e0.y;
            acc[i][2] = -0.5f * e0.z; acc[i][3] = -0.5f * e0.w;
            acc[i][4] = -0.5f * e1.x; acc[i][5] = -0.5f * e1.y;
            acc[i][6] = -0.5f * e1.z; acc[i][7] = -0.5f * e1.w;
        }

        #pragma unroll 8
        for (int d = 0; d < 64; d++) {
            float4 av = xs4[d * 32 + ty];
            float4 b0 = es4[d * 16 + tx * 2];
            float4 b1 = es4[d * 16 + tx * 2 + 1];
            float a[4] = {av.x, av.y, av.z, av.w};
            float b[8] = {b0.x, b0.y, b0.z, b0.w, b1.x, b1.y, b1.z, b1.w};
            #pragma unroll
            for (int i = 0; i < 4; i++)
                #pragma unroll
                for (int j = 0; j < 8; j++)
                    acc[i][j] = fmaf(a[i], b[j], acc[i][j]);
        }

        #pragma unroll
        for (int j = 0; j < 8; j++) {
            int kg = ck * 64 + tx * 8 + j;
            #pragma unroll
            for (int i = 0; i < 4; i++) {
                if (acc[i][j] > bestv[i]) { bestv[i] = acc[i][j]; besti[i] = kg; }
            }
        }
    }

    #pragma unroll
    for (int i = 0; i < 4; i++) {
        float v = bestv[i];
        int   ix = besti[i];
        #pragma unroll
        for (int o = 4; o; o >>= 1) {
            float v2 = __shfl_xor_sync(0xffffffffu, v, o);
            int   i2 = __shfl_xor_sync(0xffffffffu, ix, o);
            if (v2 > v || (v2 == v && i2 < ix)) { v = v2; ix = i2; }
        }
        if (tx == 0) {
            int n = p0 + ty * 4 + i;
            g_idx[n] = ix;
            out[IDX_OFF + n] = (float)ix;
        }
    }
}

// ---------------------------------------------------------------------------
// Kernel 3: quantize (gather), loss partial, EMA scatter-add. float4 per thread.
// ---------------------------------------------------------------------------
__global__ void quant_kernel(const float* __restrict__ in, float* __restrict__ out) {
    int e4 = blockIdx.x * 256 + threadIdx.x;   // float4 index, 0..2097151
    int e  = e4 * 4;
    int b   = e >> 18;
    int rem = e & 262143;
    int c   = rem >> 12;
    int hw  = rem & 4095;
    int n = b * 4096 + hw;                     // 4 consecutive pixels

    int4   r4 = *(const int4*)(g_idx + n);
    float4 x4 = ((const float4*)in)[e4];

    float4 q4;
    q4.x = g_embT[c * 1024 + r4.x];
    q4.y = g_embT[c * 1024 + r4.y];
    q4.z = g_embT[c * 1024 + r4.z];
    q4.w = g_embT[c * 1024 + r4.w];
    ((float4*)(out + QUANT_OFF))[e4] = q4;

    float dx = q4.x - x4.x, dy = q4.y - x4.y, dz = q4.z - x4.z, dw = q4.w - x4.w;
    float s = dx * dx + dy * dy + dz * dz + dw * dw;

    atomicAdd(&g_dw[r4.x * 64 + c], x4.x);
    atomicAdd(&g_dw[r4.y * 64 + c], x4.y);
    atomicAdd(&g_dw[r4.z * 64 + c], x4.z);
    atomicAdd(&g_dw[r4.w * 64 + c], x4.w);
    if (c == 0) {
        atomicAdd(&g_counts[r4.x], 1.0f);
        atomicAdd(&g_counts[r4.y], 1.0f);
        atomicAdd(&g_counts[r4.z], 1.0f);
        atomicAdd(&g_counts[r4.w], 1.0f);
    }

    #pragma unroll
    for (int o = 16; o; o >>= 1) s += __shfl_down_sync(0xffffffffu, s, o);
    __shared__ float sm[8];
    if ((threadIdx.x & 31) == 0) sm[threadIdx.x >> 5] = s;
    __syncthreads();
    if (threadIdx.x == 0) {
        float tot = 0.0f;
        #pragma unroll
        for (int i = 0; i < 8; i++) tot += sm[i];
        atomicAdd(&g_loss, tot);
    }
}

// ---------------------------------------------------------------------------
// Kernel 4a: scalars — new_cluster_size, perplexity, loss, scale factors
// ---------------------------------------------------------------------------
__global__ void scalar_kernel(const float* __restrict__ ema_cs,
                              float* __restrict__ out) {
    __shared__ float s1[1024];
    __shared__ float s2[1024];
    int k = threadIdx.x;

    float cnt = g_counts[k];
    float ncs = 0.99f * ema_cs[k] + 0.01f * cnt;
    out[NCS_OFF + k] = ncs;

    float p = cnt * (1.0f / 131072.0f);
    s1[k] = ncs;
    s2[k] = p * logf(p + 1e-10f);
    __syncthreads();
    for (int o = 512; o; o >>= 1) {
        if (k < o) { s1[k] += s1[k + o]; s2[k] += s2[k + o]; }
        __syncthreads();
    }
    float nsum = s1[0];
    float csz = (ncs + 1e-5f) / (nsum + 1024.0f * 1e-5f) * nsum;
    g_scl[k] = fmaxf(csz, 1e-5f);

    if (k == 0) {
        out[LOSS_OFF] = 0.25f * g_loss * (1.0f / 8388608.0f);
        out[PERP_OFF] = expf(-s2[0]);
    }
}

// ---------------------------------------------------------------------------
// Kernel 4b: wide EMA-w / new-embed update
// ---------------------------------------------------------------------------
__global__ void ema_kernel(const float* __restrict__ ema_w,
                           float* __restrict__ out) {
    int e = blockIdx.x * 512 + threadIdx.x;   // 0..65535
    int kk = e >> 6;
    float w = 0.99f * ema_w[e] + 0.01f * g_dw[e];
    out[NEMA_OFF + e] = w;
    out[NEMB_OFF + e] = w / g_scl[kk];
}

// ---------------------------------------------------------------------------
extern "C" void kernel_launch(void* const* d_in, const int* in_sizes, int n_in,
                              void* d_out, int out_size) {
    const float* in    = (const float*)d_in[0];
    const float* embed = (const float*)d_in[1];
    const float* ecs   = (const float*)d_in[2];
    const float* emw   = (const float*)d_in[3];
    float* out = (float*)d_out;

    prep_kernel<<<1024, 64>>>(embed);

    cudaError_t attr_ok = cudaFuncSetAttribute(
        argmin_dyn, cudaFuncAttributeMaxDynamicSharedMemorySize, ARGMIN_SMEM);
    if (attr_ok == cudaSuccess) {
        argmin_dyn<<<512, 256, ARGMIN_SMEM>>>(in, out);
    } else {
        argmin_static<<<1024, 256>>>(in, out);
    }

    quant_kernel<<<8192, 256>>>(in, out);
    scalar_kernel<<<1, 1024>>>(ecs, out);
    ema_kernel<<<128, 512>>>(emw, out);
}

// round 7
// speedup vs baseline: 1.0951x; 1.0951x over previous
#include <cuda_runtime.h>
#include <math.h>
#include <stdint.h>

#define N_PIX   131072
#define TAU     0.004f

// Output layout offsets (flattened tuple, float32) — total 8651778
#define QUANT_OFF 0
#define LOSS_OFF  8388608
#define PERP_OFF  8388609
#define IDX_OFF   8388610
#define NCS_OFF   8519682
#define NEMA_OFF  8520706
#define NEMB_OFF  8586242

// Scratch (device globals; no allocation allowed)
__device__ int   g_idx[N_PIX];
__device__ float g_embT[64 * 1024];                 // embT[d][k]
__device__ float g_esq[1024];
__device__ float g_esqh[1024];                      // -0.5*||e||^2
__device__ float g_counts[1024];
__device__ float g_dw[1024 * 64];
__device__ float g_scl[1024];
__device__ float g_loss;
__device__ __align__(128) float g_Bhi[64 * 1024];   // tf32-hi, [d][k]
__device__ __align__(128) float g_Blo[64 * 1024];   // tf32-lo, [d][k]
__device__ int   g_fb_list[N_PIX];
__device__ int   g_fb_count;
__device__ int   g_fb_take;

// ---------------------------------------------------------------------------
// helpers (base-PTX only; no sm_103a-gated features)
// ---------------------------------------------------------------------------
__device__ __forceinline__ uint32_t smem_u32(const void* p) {
    uint32_t a;
    asm("{ .reg .u64 t; cvta.to.shared.u64 t, %1; cvt.u32.u64 %0, t; }" : "=r"(a) : "l"(p));
    return a;
}
__device__ __forceinline__ uint32_t cvt_tf32(float v) {
    uint32_t r;
    asm("cvt.rna.tf32.f32 %0, %1;" : "=r"(r) : "f"(v));
    return r;
}
__device__ __forceinline__ void mma8(float& d0, float& d1, float& d2, float& d3,
                                     uint32_t a0, uint32_t a1, uint32_t a2, uint32_t a3,
                                     uint32_t b0, uint32_t b1) {
    asm volatile(
        "mma.sync.aligned.m16n8k8.row.col.f32.tf32.tf32.f32 "
        "{%0,%1,%2,%3}, {%4,%5,%6,%7}, {%8,%9}, {%0,%1,%2,%3};"
        : "+f"(d0), "+f"(d1), "+f"(d2), "+f"(d3)
        : "r"(a0), "r"(a1), "r"(a2), "r"(a3), "r"(b0), "r"(b1));
}
#define CP_ASYNC16(dst, src) \
    asm volatile("cp.async.cg.shared.global [%0], [%1], 16;" :: "r"(dst), "l"(src) : "memory")
#define CP_COMMIT() asm volatile("cp.async.commit_group;" ::: "memory")
#define CP_WAIT1()  asm volatile("cp.async.wait_group 1;" ::: "memory")
#define CP_WAIT0()  asm volatile("cp.async.wait_group 0;" ::: "memory")

// best-2 running update (strict > keeps lowest index; codes ascend)
__device__ __forceinline__ void upd(float& b1, int& i1, float& b2, float s, int idx) {
    if (s > b1) { b2 = b1; b1 = s; i1 = idx; }
    else if (s > b2) { b2 = s; }
}

// ---------------------------------------------------------------------------
// Kernel 1: prep — embT, esq, split-tf32 codebook, zero accumulators
// grid 1024 (code k), 64 threads (channel d)
// ---------------------------------------------------------------------------
__global__ void prep_kernel(const float* __restrict__ embed) {
    int k = blockIdx.x;
    int t = threadIdx.x;
    float v = embed[k * 64 + t];
    g_embT[t * 1024 + k] = v;
    g_dw[k * 64 + t] = 0.0f;

    uint32_t hb = cvt_tf32(v);
    float hi = __uint_as_float(hb);
    g_Bhi[t * 1024 + k] = hi;
    g_Blo[t * 1024 + k] = __uint_as_float(cvt_tf32(v - hi));

    float s = v * v;
    #pragma unroll
    for (int o = 16; o; o >>= 1) s += __shfl_down_sync(0xffffffffu, s, o);
    __shared__ float sm[2];
    if ((t & 31) == 0) sm[t >> 5] = s;
    __syncthreads();
    if (t == 0) {
        float e = sm[0] + sm[1];
        g_esq[k] = e;
        g_esqh[k] = -0.5f * e;
        g_counts[k] = 0.0f;
        if (k == 0) { g_loss = 0.0f; g_fb_count = 0; g_fb_take = 0; }
    }
}

// ---------------------------------------------------------------------------
// Kernel 2 (primary): split-TF32 argmin via mma.sync (register accumulators).
// 1024 blocks x 256 threads (8 warps). Block = 128 pixels; warp = 16 pixels.
// Codes in 16 chunks of 64, double-buffered via cp.async.
// smem: B[2 buf][2 split][64 k][72 pad] floats (73728B) + esqh[1024] (4096B)
// ---------------------------------------------------------------------------
#define BSTRIDE 72
#define SMEM_MM (73728 + 4096)

__global__ void __launch_bounds__(256, 2) argmin_mma(const float* __restrict__ in,
                                                     float* __restrict__ out) {
    extern __shared__ char sm[];
    float* bsf  = (float*)sm;
    float* esqs = (float*)(sm + 73728);
    uint32_t smb = smem_u32(sm);

    const int tid = threadIdx.x;
    const int w   = tid >> 5;       // warp 0..7
    const int ln  = tid & 31;
    const int g   = ln >> 2;        // group 0..7
    const int t   = ln & 3;
    const int p0  = blockIdx.x * 128;
    const int bimg = p0 >> 12;
    const int hw0  = p0 & 4095;

    // ---- issue chunk 0 B copy ----
    {
        #pragma unroll
        for (int j = 0; j < 8; j++) {
            int idx = tid + j * 256;             // 0..2047
            int s = idx >> 10, rem = idx & 1023;
            int k = rem >> 4, f4 = rem & 15;
            const float* src = (s ? g_Blo : g_Bhi) + k * 1024 + f4 * 4;
            uint32_t dst = smb + ((s * 64 + k) * BSTRIDE + f4 * 4) * 4;
            CP_ASYNC16(dst, src);
        }
        CP_COMMIT();
    }

    // ---- esqh table ----
    #pragma unroll
    for (int i = 0; i < 4; i++) esqs[tid + i * 256] = g_esqh[tid + i * 256];

    // ---- A fragments: 16 pixels x 64 channels, split tf32, in registers ----
    // a0:(row g, col kk*8+t) a1:(g+8, same) a2:(g, +4) a3:(g+8, +4)
    uint32_t ah[8][4], al[8][4];
    {
        const float* ap = in + (size_t)bimg * 262144 + hw0 + w * 16 + g;
        #pragma unroll
        for (int kk = 0; kk < 8; kk++) {
            float x0 = ap[(kk * 8 + t) * 4096];
            float x1 = ap[(kk * 8 + t) * 4096 + 8];
            float x2 = ap[(kk * 8 + t + 4) * 4096];
            float x3 = ap[(kk * 8 + t + 4) * 4096 + 8];
            ah[kk][0] = cvt_tf32(x0); al[kk][0] = cvt_tf32(x0 - __uint_as_float(ah[kk][0]));
            ah[kk][1] = cvt_tf32(x1); al[kk][1] = cvt_tf32(x1 - __uint_as_float(ah[kk][1]));
            ah[kk][2] = cvt_tf32(x2); al[kk][2] = cvt_tf32(x2 - __uint_as_float(ah[kk][2]));
            ah[kk][3] = cvt_tf32(x3); al[kk][3] = cvt_tf32(x3 - __uint_as_float(ah[kk][3]));
        }
    }

    float b1a = -3.4e38f, b2a = -3.4e38f; int i1a = 0;   // pixel row g
    float b1b = -3.4e38f, b2b = -3.4e38f; int i1b = 0;   // pixel row g+8

    for (int c = 0; c < 16; c++) {
        const int buf = c & 1;
        if (c < 15) {   // prefetch next chunk into other buffer
            int nb = (c + 1) & 1;
            #pragma unroll
            for (int j = 0; j < 8; j++) {
                int idx = tid + j * 256;
                int s = idx >> 10, rem = idx & 1023;
                int k = rem >> 4, f4 = rem & 15;
                const float* src = (s ? g_Blo : g_Bhi) + k * 1024 + (c + 1) * 64 + f4 * 4;
                uint32_t dst = smb + (((nb * 2 + s) * 64 + k) * BSTRIDE + f4 * 4) * 4;
                CP_ASYNC16(dst, src);
            }
            CP_COMMIT();
            CP_WAIT1();
        } else {
            CP_WAIT0();
        }
        __syncthreads();

        const float* bh = bsf + (buf * 2 + 0) * 64 * BSTRIDE;
        const float* bl = bsf + (buf * 2 + 1) * 64 * BSTRIDE;
        const int kbase = c * 64;

        #pragma unroll
        for (int nt = 0; nt < 8; nt++) {
            float c0 = 0.f, c1 = 0.f, c2 = 0.f, c3 = 0.f;
            const int nb_ = nt * 8 + g;
            #pragma unroll
            for (int kk = 0; kk < 8; kk++) {
                int kr = kk * 8 + t;
                uint32_t bh0 = __float_as_uint(bh[kr * BSTRIDE + nb_]);
                uint32_t bh1 = __float_as_uint(bh[(kr + 4) * BSTRIDE + nb_]);
                uint32_t bl0 = __float_as_uint(bl[kr * BSTRIDE + nb_]);
                uint32_t bl1 = __float_as_uint(bl[(kr + 4) * BSTRIDE + nb_]);
                mma8(c0, c1, c2, c3, ah[kk][0], ah[kk][1], ah[kk][2], ah[kk][3], bh0, bh1);
                mma8(c0, c1, c2, c3, al[kk][0], al[kk][1], al[kk][2], al[kk][3], bh0, bh1);
                mma8(c0, c1, c2, c3, ah[kk][0], ah[kk][1], ah[kk][2], ah[kk][3], bl0, bl1);
            }
            // epilogue: lane holds codes (2t, 2t+1) for pixels g / g+8
            int code0 = kbase + nt * 8 + 2 * t;
            float e0 = esqs[code0], e1 = esqs[code0 + 1];
            upd(b1a, i1a, b2a, c0 + e0, code0);
            upd(b1a, i1a, b2a, c1 + e1, code0 + 1);
            upd(b1b, i1b, b2b, c2 + e0, code0);
            upd(b1b, i1b, b2b, c3 + e1, code0 + 1);
        }
        __syncthreads();   // all warps done with buf before it is overwritten
    }

    // reduce across the 4 lanes of the group (t = 0..3)
    #pragma unroll
    for (int o = 1; o <= 2; o <<= 1) {
        float ob1 = __shfl_xor_sync(0xffffffffu, b1a, o);
        float ob2 = __shfl_xor_sync(0xffffffffu, b2a, o);
        int   oi1 = __shfl_xor_sync(0xffffffffu, i1a, o);
        if (ob1 > b1a || (ob1 == b1a && oi1 < i1a)) { b2a = fmaxf(b1a, ob2); b1a = ob1; i1a = oi1; }
        else { b2a = fmaxf(b2a, ob1); }
        ob1 = __shfl_xor_sync(0xffffffffu, b1b, o);
        ob2 = __shfl_xor_sync(0xffffffffu, b2b, o);
        oi1 = __shfl_xor_sync(0xffffffffu, i1b, o);
        if (ob1 > b1b || (ob1 == b1b && oi1 < i1b)) { b2b = fmaxf(b1b, ob2); b1b = ob1; i1b = oi1; }
        else { b2b = fmaxf(b2b, ob1); }
    }

    if (t == 0) {
        int n = p0 + w * 16 + g;
        g_idx[n] = i1a;
        out[IDX_OFF + n] = (float)i1a;
        if (b1a - b2a < TAU) g_fb_list[atomicAdd(&g_fb_count, 1)] = n;
        int n2 = n + 8;
        g_idx[n2] = i1b;
        out[IDX_OFF + n2] = (float)i1b;
        if (b1b - b2b < TAU) g_fb_list[atomicAdd(&g_fb_count, 1)] = n2;
    }
}

// ---------------------------------------------------------------------------
// Kernel 2b: exact fp32 fallback for ambiguous pixels (rare)
// ---------------------------------------------------------------------------
__global__ void fb_kernel(const float* __restrict__ in,
                          const float* __restrict__ embed,
                          float* __restrict__ out) {
    __shared__ float xs[64];
    __shared__ float rv[256];
    __shared__ int   ri[256];
    __shared__ int   cur;
    while (true) {
        if (threadIdx.x == 0) cur = atomicAdd(&g_fb_take, 1);
        __syncthreads();
        int i = cur;
        if (i >= g_fb_count) break;
        int n = g_fb_list[i];
        int b = n >> 12, hw = n & 4095;
        if (threadIdx.x < 64)
            xs[threadIdx.x] = in[(size_t)b * 262144 + threadIdx.x * 4096 + hw];
        __syncthreads();

        int k0 = threadIdx.x * 4;
        float bv = -3.4e38f; int bi = 0;
        for (int k = k0; k < k0 + 4; k++) {
            const float* e = embed + k * 64;
            float s = g_esqh[k];
            #pragma unroll
            for (int c = 0; c < 64; c++) s = fmaf(xs[c], e[c], s);
            if (s > bv) { bv = s; bi = k; }
        }
        rv[threadIdx.x] = bv; ri[threadIdx.x] = bi;
        __syncthreads();
        for (int o = 128; o; o >>= 1) {
            if (threadIdx.x < o) {
                float v2 = rv[threadIdx.x + o]; int i2 = ri[threadIdx.x + o];
                if (v2 > rv[threadIdx.x] || (v2 == rv[threadIdx.x] && i2 < ri[threadIdx.x])) {
                    rv[threadIdx.x] = v2; ri[threadIdx.x] = i2;
                }
            }
            __syncthreads();
        }
        if (threadIdx.x == 0) { g_idx[n] = ri[0]; out[IDX_OFF + n] = (float)ri[0]; }
        __syncthreads();
    }
}

// ---------------------------------------------------------------------------
// Kernel 2 (alt): proven CUDA-core argmin (used if smem attr fails)
// ---------------------------------------------------------------------------
__global__ void __launch_bounds__(256) argmin_static(const float* __restrict__ in,
                                                     float* __restrict__ out) {
    __shared__ float4 xs4[2048];
    __shared__ float4 es4[1024];
    const int tid = threadIdx.x;
    const int tx = tid & 7, ty = tid >> 3;
    const int p0 = blockIdx.x * 128;
    const int bimg = p0 >> 12, hw0 = p0 & 4095;

    const float4* in4 = (const float4*)(in + (size_t)bimg * 262144 + hw0);
    #pragma unroll
    for (int tt = 0; tt < 8; tt++) {
        int i = tid + tt * 256;
        xs4[i] = in4[(i >> 5) * 1024 + (i & 31)];
    }
    float bestv[4]; int besti[4];
    #pragma unroll
    for (int i = 0; i < 4; i++) { bestv[i] = -3.4e38f; besti[i] = 0; }
    const float4* embT4 = (const float4*)g_embT;
    const float4* esq4 = (const float4*)g_esq;

    for (int ck = 0; ck < 16; ck++) {
        __syncthreads();
        #pragma unroll
        for (int tt = 0; tt < 4; tt++) {
            int i = tid + tt * 256;
            es4[i] = embT4[(i >> 4) * 256 + ck * 16 + (i & 15)];
        }
        __syncthreads();
        float4 e0 = esq4[ck * 16 + tx * 2], e1 = esq4[ck * 16 + tx * 2 + 1];
        float acc[4][8];
        #pragma unroll
        for (int i = 0; i < 4; i++) {
            acc[i][0] = -0.5f * e0.x; acc[i][1] = -0.5f * e0.y; acc[i][2] = -0.5f * e0.z; acc[i][3] = -0.5f * e0.w;
            acc[i][4] = -0.5f * e1.x; acc[i][5] = -0.5f * e1.y; acc[i][6] = -0.5f * e1.z; acc[i][7] = -0.5f * e1.w;
        }
        #pragma unroll 8
        for (int d = 0; d < 64; d++) {
            float4 av = xs4[d * 32 + ty];
            float4 b0 = es4[d * 16 + tx * 2], b1v = es4[d * 16 + tx * 2 + 1];
            float a[4] = {av.x, av.y, av.z, av.w};
            float b[8] = {b0.x, b0.y, b0.z, b0.w, b1v.x, b1v.y, b1v.z, b1v.w};
            #pragma unroll
            for (int i = 0; i < 4; i++)
                #pragma unroll
                for (int j = 0; j < 8; j++) acc[i][j] = fmaf(a[i], b[j], acc[i][j]);
        }
        #pragma unroll
        for (int j = 0; j < 8; j++) {
            int kg = ck * 64 + tx * 8 + j;
            #pragma unroll
            for (int i = 0; i < 4; i++)
                if (acc[i][j] > bestv[i]) { bestv[i] = acc[i][j]; besti[i] = kg; }
        }
    }
    #pragma unroll
    for (int i = 0; i < 4; i++) {
        float v = bestv[i]; int ix = besti[i];
        #pragma unroll
        for (int o = 4; o; o >>= 1) {
            float v2 = __shfl_xor_sync(0xffffffffu, v, o);
            int i2 = __shfl_xor_sync(0xffffffffu, ix, o);
            if (v2 > v || (v2 == v && i2 < ix)) { v = v2; ix = i2; }
        }
        if (tx == 0) {
            int n = p0 + ty * 4 + i;
            g_idx[n] = ix;
            out[IDX_OFF + n] = (float)ix;
        }
    }
}

// ---------------------------------------------------------------------------
// Kernel 3: quantize (gather), loss partial, EMA scatter-add (float4/thread)
// ---------------------------------------------------------------------------
__global__ void quant_kernel(const float* __restrict__ in, float* __restrict__ out) {
    int e4 = blockIdx.x * 256 + threadIdx.x;
    int e = e4 * 4;
    int b = e >> 18, rem = e & 262143, c = rem >> 12, hw = rem & 4095;
    int n = b * 4096 + hw;

    int4 r4 = *(const int4*)(g_idx + n);
    float4 x4 = ((const float4*)in)[e4];
    float4 q4;
    q4.x = g_embT[c * 1024 + r4.x];
    q4.y = g_embT[c * 1024 + r4.y];
    q4.z = g_embT[c * 1024 + r4.z];
    q4.w = g_embT[c * 1024 + r4.w];
    ((float4*)(out + QUANT_OFF))[e4] = q4;

    float dx = q4.x - x4.x, dy = q4.y - x4.y, dz = q4.z - x4.z, dw = q4.w - x4.w;
    float s = dx * dx + dy * dy + dz * dz + dw * dw;

    atomicAdd(&g_dw[r4.x * 64 + c], x4.x);
    atomicAdd(&g_dw[r4.y * 64 + c], x4.y);
    atomicAdd(&g_dw[r4.z * 64 + c], x4.z);
    atomicAdd(&g_dw[r4.w * 64 + c], x4.w);
    if (c == 0) {
        atomicAdd(&g_counts[r4.x], 1.0f);
        atomicAdd(&g_counts[r4.y], 1.0f);
        atomicAdd(&g_counts[r4.z], 1.0f);
        atomicAdd(&g_counts[r4.w], 1.0f);
    }
    #pragma unroll
    for (int o = 16; o; o >>= 1) s += __shfl_down_sync(0xffffffffu, s, o);
    __shared__ float sm[8];
    if ((threadIdx.x & 31) == 0) sm[threadIdx.x >> 5] = s;
    __syncthreads();
    if (threadIdx.x == 0) {
        float tot = 0.0f;
        #pragma unroll
        for (int i = 0; i < 8; i++) tot += sm[i];
        atomicAdd(&g_loss, tot);
    }
}

// ---------------------------------------------------------------------------
// Kernel 4a: scalars
// ---------------------------------------------------------------------------
__global__ void scalar_kernel(const float* __restrict__ ema_cs, float* __restrict__ out) {
    __shared__ float s1[1024];
    __shared__ float s2[1024];
    int k = threadIdx.x;
    float cnt = g_counts[k];
    float ncs = 0.99f * ema_cs[k] + 0.01f * cnt;
    out[NCS_OFF + k] = ncs;
    float p = cnt * (1.0f / 131072.0f);
    s1[k] = ncs;
    s2[k] = p * logf(p + 1e-10f);
    __syncthreads();
    for (int o = 512; o; o >>= 1) {
        if (k < o) { s1[k] += s1[k + o]; s2[k] += s2[k + o]; }
        __syncthreads();
    }
    float nsum = s1[0];
    float csz = (ncs + 1e-5f) / (nsum + 1024.0f * 1e-5f) * nsum;
    g_scl[k] = fmaxf(csz, 1e-5f);
    if (k == 0) {
        out[LOSS_OFF] = 0.25f * g_loss * (1.0f / 8388608.0f);
        out[PERP_OFF] = expf(-s2[0]);
    }
}

// ---------------------------------------------------------------------------
// Kernel 4b: wide EMA update
// ---------------------------------------------------------------------------
__global__ void ema_kernel(const float* __restrict__ ema_w, float* __restrict__ out) {
    int e = blockIdx.x * 512 + threadIdx.x;
    int kk = e >> 6;
    float w = 0.99f * ema_w[e] + 0.01f * g_dw[e];
    out[NEMA_OFF + e] = w;
    out[NEMB_OFF + e] = w / g_scl[kk];
}

// ---------------------------------------------------------------------------
extern "C" void kernel_launch(void* const* d_in, const int* in_sizes, int n_in,
                              void* d_out, int out_size) {
    const float* in    = (const float*)d_in[0];
    const float* embed = (const float*)d_in[1];
    const float* ecs   = (const float*)d_in[2];
    const float* emw   = (const float*)d_in[3];
    float* out = (float*)d_out;

    prep_kernel<<<1024, 64>>>(embed);

    cudaError_t ok = cudaFuncSetAttribute(
        argmin_mma, cudaFuncAttributeMaxDynamicSharedMemorySize, SMEM_MM);
    if (ok == cudaSuccess) {
        argmin_mma<<<1024, 256, SMEM_MM>>>(in, out);
        fb_kernel<<<296, 256>>>(in, embed, out);
    } else {
        argmin_static<<<1024, 256>>>(in, out);
    }

    quant_kernel<<<8192, 256>>>(in, out);
    scalar_kernel<<<1, 1024>>>(ecs, out);
    ema_kernel<<<128, 512>>>(emw, out);
}

// round 8
// speedup vs baseline: 1.4679x; 1.3404x over previous
#include <cuda_runtime.h>
#include <cuda_fp16.h>
#include <math.h>
#include <stdint.h>

#define N_PIX   131072
#define TAU     0.002f

// Output layout offsets (flattened tuple, float32) — total 8651778
#define QUANT_OFF 0
#define LOSS_OFF  8388608
#define PERP_OFF  8388609
#define IDX_OFF   8388610
#define NCS_OFF   8519682
#define NEMA_OFF  8520706
#define NEMB_OFF  8586242

// Scratch (device globals; no allocation allowed)
__device__ int   g_idx[N_PIX];
__device__ float g_esqh[1024];                       // -0.5*||e||^2
__device__ float g_counts[1024];
__device__ float g_dw[1024 * 64];
__device__ float g_scl[1024];
__device__ float g_loss;
// packed split-fp16 codebook: [chunk 16][split 2][kstep 4][n 64][j 8] half2
__device__ __align__(128) __half g_Bpk[16 * 8192];
__device__ int   g_fb_list[N_PIX];
__device__ int   g_fb_count;
__device__ int   g_fb_take;

// ---------------------------------------------------------------------------
// helpers (base PTX only)
// ---------------------------------------------------------------------------
__device__ __forceinline__ uint32_t smem_u32(const void* p) {
    uint32_t a;
    asm("{ .reg .u64 t; cvta.to.shared.u64 t, %1; cvt.u32.u64 %0, t; }" : "=r"(a) : "l"(p));
    return a;
}
__device__ __forceinline__ void mma16(float& d0, float& d1, float& d2, float& d3,
                                      const uint32_t* a, uint32_t b0, uint32_t b1) {
    asm volatile(
        "mma.sync.aligned.m16n8k16.row.col.f32.f16.f16.f32 "
        "{%0,%1,%2,%3}, {%4,%5,%6,%7}, {%8,%9}, {%0,%1,%2,%3};"
        : "+f"(d0), "+f"(d1), "+f"(d2), "+f"(d3)
        : "r"(a[0]), "r"(a[1]), "r"(a[2]), "r"(a[3]), "r"(b0), "r"(b1));
}
#define CP_ASYNC16(dst, src) \
    asm volatile("cp.async.cg.shared.global [%0], [%1], 16;" :: "r"(dst), "l"(src) : "memory")
#define CP_COMMIT() asm volatile("cp.async.commit_group;" ::: "memory")
#define CP_WAIT1()  asm volatile("cp.async.wait_group 1;" ::: "memory")
#define CP_WAIT0()  asm volatile("cp.async.wait_group 0;" ::: "memory")

__device__ __forceinline__ uint32_t packsplit(float x0, float x1, uint32_t& lo) {
    __half h0 = __float2half_rn(x0), h1 = __float2half_rn(x1);
    __half l0 = __float2half_rn(x0 - __half2float(h0));
    __half l1 = __float2half_rn(x1 - __half2float(h1));
    __half2 hh = __halves2half2(h0, h1), ll = __halves2half2(l0, l1);
    lo = *(uint32_t*)&ll;
    return *(uint32_t*)&hh;
}
// best-2 running update (strict > keeps lowest index; codes ascend)
__device__ __forceinline__ void upd(float& b1, int& i1, float& b2, float s, int idx) {
    if (s > b1) { b2 = b1; b1 = s; i1 = idx; }
    else if (s > b2) { b2 = s; }
}

// ---------------------------------------------------------------------------
// Kernel 1: prep — split-fp16 packed codebook, esqh, zero accumulators
// grid 1024 (code k), 64 threads (channel d)
// ---------------------------------------------------------------------------
__global__ void prep_kernel(const float* __restrict__ embed) {
    int k = blockIdx.x;
    int t = threadIdx.x;
    float v = embed[k * 64 + t];
    g_dw[k * 64 + t] = 0.0f;

    __half hi = __float2half_rn(v);
    __half lo = __float2half_rn(v - __half2float(hi));
    // pack layout: halves index = chunk*8192 + ((split*4+s)*64+n)*16 + j*2 + h
    // pair p covers k_local = 16s + 2p..+1 ; j order {0,4,1,5,2,6,3,7}
    int c = k >> 6, n = k & 63, s = t >> 4, dl = t & 15, p = dl >> 1, h = dl & 1;
    int j = ((p & 3) << 1) | (p >> 2);
    int base = c * 8192;
    g_Bpk[base + (s * 64 + n) * 16 + j * 2 + h] = hi;
    g_Bpk[base + ((4 + s) * 64 + n) * 16 + j * 2 + h] = lo;

    float sq = v * v;
    #pragma unroll
    for (int o = 16; o; o >>= 1) sq += __shfl_down_sync(0xffffffffu, sq, o);
    __shared__ float sm[2];
    if ((t & 31) == 0) sm[t >> 5] = sq;
    __syncthreads();
    if (t == 0) {
        g_esqh[k] = -0.5f * (sm[0] + sm[1]);
        g_counts[k] = 0.0f;
        if (k == 0) { g_loss = 0.0f; g_fb_count = 0; g_fb_take = 0; }
    }
}

// ---------------------------------------------------------------------------
// Kernel 2: split-FP16 argmin via mma.sync m16n8k16 (register accumulators).
// 1024 blocks x 256 threads (8 warps). Block = 128 pixels; warp = 16 pixels.
// Codes in 16 chunks of 64, double-buffered cp.async. Static smem 36KB.
// Tracks s = x.e - 0.5*||e||^2 ; argmin dist == argmax s.
// ---------------------------------------------------------------------------
__global__ void __launch_bounds__(256) argmin_mma(const float* __restrict__ in,
                                                  float* __restrict__ out) {
    __shared__ __align__(16) __half Bsm[16384];   // 2 bufs x 16KB
    __shared__ float esqs[1024];
    uint32_t smb = smem_u32(Bsm);

    const int tid = threadIdx.x;
    const int w   = tid >> 5;
    const int ln  = tid & 31;
    const int g   = ln >> 2;
    const int t   = ln & 3;
    const int p0  = blockIdx.x * 128;
    const int bimg = p0 >> 12;
    const int hw0  = p0 & 4095;

    // chunk 0 -> buf 0
    #pragma unroll
    for (int jj = 0; jj < 4; jj++) {
        int idx = tid + jj * 256;
        CP_ASYNC16(smb + idx * 16, (const char*)g_Bpk + idx * 16);
    }
    CP_COMMIT();

    #pragma unroll
    for (int i = 0; i < 4; i++) esqs[tid + i * 256] = g_esqh[tid + i * 256];

    // A fragments: 16 pixels x 64 ch, split fp16, in registers
    uint32_t ah[4][4], al[4][4];
    {
        const float* ap = in + (size_t)bimg * 262144 + hw0 + w * 16 + g;
        #pragma unroll
        for (int s = 0; s < 4; s++) {
            int d0 = 16 * s + 2 * t;
            ah[s][0] = packsplit(ap[d0 * 4096],          ap[(d0 + 1) * 4096],     al[s][0]); // row g
            ah[s][1] = packsplit(ap[d0 * 4096 + 8],      ap[(d0 + 1) * 4096 + 8], al[s][1]); // row g+8
            ah[s][2] = packsplit(ap[(d0 + 8) * 4096],    ap[(d0 + 9) * 4096],     al[s][2]);
            ah[s][3] = packsplit(ap[(d0 + 8) * 4096 + 8],ap[(d0 + 9) * 4096 + 8], al[s][3]);
        }
    }

    float b1a = -3.4e38f, b2a = -3.4e38f; int i1a = 0;   // pixel row g
    float b1b = -3.4e38f, b2b = -3.4e38f; int i1b = 0;   // pixel row g+8

    for (int c = 0; c < 16; c++) {
        const int buf = c & 1;
        if (c < 15) {
            int nb = (c + 1) & 1;
            #pragma unroll
            for (int jj = 0; jj < 4; jj++) {
                int idx = tid + jj * 256;
                CP_ASYNC16(smb + nb * 16384 + idx * 16,
                           (const char*)g_Bpk + (c + 1) * 16384 + idx * 16);
            }
            CP_COMMIT();
            CP_WAIT1();
        } else {
            CP_WAIT0();
        }
        __syncthreads();

        const uint32_t bb = smb + buf * 16384;
        const int kbase = c * 64;

        #pragma unroll
        for (int nt = 0; nt < 8; nt++) {
            float c0 = 0.f, c1 = 0.f, c2 = 0.f, c3 = 0.f;
            const int nb_ = nt * 8 + g;
            #pragma unroll
            for (int s = 0; s < 4; s++) {
                uint32_t offh = bb + (s * 64 + nb_) * 32 + 8 * t;
                uint32_t offl = offh + 8192;             // split=1 half of chunk
                uint32_t bh0, bh1, bl0, bl1;
                asm volatile("ld.shared.v2.b32 {%0,%1}, [%2];" : "=r"(bh0), "=r"(bh1) : "r"(offh));
                asm volatile("ld.shared.v2.b32 {%0,%1}, [%2];" : "=r"(bl0), "=r"(bl1) : "r"(offl));
                mma16(c0, c1, c2, c3, ah[s], bh0, bh1);
                mma16(c0, c1, c2, c3, al[s], bh0, bh1);
                mma16(c0, c1, c2, c3, ah[s], bl0, bl1);
            }
            int code0 = kbase + nt * 8 + 2 * t;
            float e0 = esqs[code0], e1 = esqs[code0 + 1];
            upd(b1a, i1a, b2a, c0 + e0, code0);
            upd(b1a, i1a, b2a, c1 + e1, code0 + 1);
            upd(b1b, i1b, b2b, c2 + e0, code0);
            upd(b1b, i1b, b2b, c3 + e1, code0 + 1);
        }
        __syncthreads();
    }

    // reduce across the 4 lanes of the group (t = 0..3)
    #pragma unroll
    for (int o = 1; o <= 2; o <<= 1) {
        float ob1 = __shfl_xor_sync(0xffffffffu, b1a, o);
        float ob2 = __shfl_xor_sync(0xffffffffu, b2a, o);
        int   oi1 = __shfl_xor_sync(0xffffffffu, i1a, o);
        if (ob1 > b1a || (ob1 == b1a && oi1 < i1a)) { b2a = fmaxf(b1a, ob2); b1a = ob1; i1a = oi1; }
        else { b2a = fmaxf(b2a, ob1); }
        ob1 = __shfl_xor_sync(0xffffffffu, b1b, o);
        ob2 = __shfl_xor_sync(0xffffffffu, b2b, o);
        oi1 = __shfl_xor_sync(0xffffffffu, i1b, o);
        if (ob1 > b1b || (ob1 == b1b && oi1 < i1b)) { b2b = fmaxf(b1b, ob2); b1b = ob1; i1b = oi1; }
        else { b2b = fmaxf(b2b, ob1); }
    }

    if (t == 0) {
        int n = p0 + w * 16 + g;
        g_idx[n] = i1a;
        out[IDX_OFF + n] = (float)i1a;
        if (b1a - b2a < TAU) g_fb_list[atomicAdd(&g_fb_count, 1)] = n;
        int n2 = n + 8;
        g_idx[n2] = i1b;
        out[IDX_OFF + n2] = (float)i1b;
        if (b1b - b2b < TAU) g_fb_list[atomicAdd(&g_fb_count, 1)] = n2;
    }
}

// ---------------------------------------------------------------------------
// Kernel 2b: exact fp32 fallback for ambiguous pixels
// ---------------------------------------------------------------------------
__global__ void fb_kernel(const float* __restrict__ in,
                          const float* __restrict__ embed,
                          float* __restrict__ out) {
    __shared__ float xs[64];
    __shared__ float rv[256];
    __shared__ int   ri[256];
    __shared__ int   cur;
    while (true) {
        if (threadIdx.x == 0) cur = atomicAdd(&g_fb_take, 1);
        __syncthreads();
        int i = cur;
        if (i >= g_fb_count) break;
        int n = g_fb_list[i];
        int b = n >> 12, hw = n & 4095;
        if (threadIdx.x < 64)
            xs[threadIdx.x] = in[(size_t)b * 262144 + threadIdx.x * 4096 + hw];
        __syncthreads();

        int k0 = threadIdx.x * 4;
        float bv = -3.4e38f; int bi = 0;
        for (int k = k0; k < k0 + 4; k++) {
            const float* e = embed + k * 64;
            float s = g_esqh[k];
            #pragma unroll
            for (int c = 0; c < 64; c++) s = fmaf(xs[c], e[c], s);
            if (s > bv) { bv = s; bi = k; }
        }
        rv[threadIdx.x] = bv; ri[threadIdx.x] = bi;
        __syncthreads();
        for (int o = 128; o; o >>= 1) {
            if (threadIdx.x < o) {
                float v2 = rv[threadIdx.x + o]; int i2 = ri[threadIdx.x + o];
                if (v2 > rv[threadIdx.x] || (v2 == rv[threadIdx.x] && i2 < ri[threadIdx.x])) {
                    rv[threadIdx.x] = v2; ri[threadIdx.x] = i2;
                }
            }
            __syncthreads();
        }
        if (threadIdx.x == 0) { g_idx[n] = ri[0]; out[IDX_OFF + n] = (float)ri[0]; }
        __syncthreads();
    }
}

// ---------------------------------------------------------------------------
// Kernel 3: quantize — one thread per PIXEL: contiguous embed-row gather,
// coalesced channel-strided in/out, consecutive-address dw REDs.
// ---------------------------------------------------------------------------
__global__ void quant_kernel(const float* __restrict__ in,
                             const float* __restrict__ embed,
                             float* __restrict__ out) {
    int n = blockIdx.x * 256 + threadIdx.x;       // pixel 0..131071
    int b = n >> 12, hw = n & 4095;
    int r = g_idx[n];

    const float4* er = (const float4*)(embed + r * 64);
    const float* ib = in + (size_t)b * 262144 + hw;
    float* ob = out + QUANT_OFF + (size_t)b * 262144 + hw;
    float* dwr = g_dw + r * 64;

    float s = 0.0f;
    #pragma unroll
    for (int j = 0; j < 16; j++) {
        float4 q = __ldg(er + j);
        int d = j * 4;
        float x0 = ib[(size_t)d * 4096];
        float x1 = ib[(size_t)(d + 1) * 4096];
        float x2 = ib[(size_t)(d + 2) * 4096];
        float x3 = ib[(size_t)(d + 3) * 4096];
        ob[(size_t)d * 4096]       = q.x;
        ob[(size_t)(d + 1) * 4096] = q.y;
        ob[(size_t)(d + 2) * 4096] = q.z;
        ob[(size_t)(d + 3) * 4096] = q.w;
        float e0 = q.x - x0, e1 = q.y - x1, e2 = q.z - x2, e3 = q.w - x3;
        s += e0 * e0 + e1 * e1 + e2 * e2 + e3 * e3;
        atomicAdd(dwr + d,     x0);
        atomicAdd(dwr + d + 1, x1);
        atomicAdd(dwr + d + 2, x2);
        atomicAdd(dwr + d + 3, x3);
    }
    atomicAdd(&g_counts[r], 1.0f);

    #pragma unroll
    for (int o = 16; o; o >>= 1) s += __shfl_down_sync(0xffffffffu, s, o);
    __shared__ float sm[8];
    if ((threadIdx.x & 31) == 0) sm[threadIdx.x >> 5] = s;
    __syncthreads();
    if (threadIdx.x == 0) {
        float tot = 0.0f;
        #pragma unroll
        for (int i = 0; i < 8; i++) tot += sm[i];
        atomicAdd(&g_loss, tot);
    }
}

// ---------------------------------------------------------------------------
// Kernel 4a: scalars
// ---------------------------------------------------------------------------
__global__ void scalar_kernel(const float* __restrict__ ema_cs, float* __restrict__ out) {
    __shared__ float s1[1024];
    __shared__ float s2[1024];
    int k = threadIdx.x;
    float cnt = g_counts[k];
    float ncs = 0.99f * ema_cs[k] + 0.01f * cnt;
    out[NCS_OFF + k] = ncs;
    float p = cnt * (1.0f / 131072.0f);
    s1[k] = ncs;
    s2[k] = p * logf(p + 1e-10f);
    __syncthreads();
    for (int o = 512; o; o >>= 1) {
        if (k < o) { s1[k] += s1[k + o]; s2[k] += s2[k + o]; }
        __syncthreads();
    }
    float nsum = s1[0];
    float csz = (ncs + 1e-5f) / (nsum + 1024.0f * 1e-5f) * nsum;
    g_scl[k] = fmaxf(csz, 1e-5f);
    if (k == 0) {
        out[LOSS_OFF] = 0.25f * g_loss * (1.0f / 8388608.0f);
        out[PERP_OFF] = expf(-s2[0]);
    }
}

// ---------------------------------------------------------------------------
// Kernel 4b: wide EMA update
// ---------------------------------------------------------------------------
__global__ void ema_kernel(const float* __restrict__ ema_w, float* __restrict__ out) {
    int e = blockIdx.x * 512 + threadIdx.x;
    int kk = e >> 6;
    float w = 0.99f * ema_w[e] + 0.01f * g_dw[e];
    out[NEMA_OFF + e] = w;
    out[NEMB_OFF + e] = w / g_scl[kk];
}

// ---------------------------------------------------------------------------
extern "C" void kernel_launch(void* const* d_in, const int* in_sizes, int n_in,
                              void* d_out, int out_size) {
    const float* in    = (const float*)d_in[0];
    const float* embed = (const float*)d_in[1];
    const float* ecs   = (const float*)d_in[2];
    const float* emw   = (const float*)d_in[3];
    float* out = (float*)d_out;

    prep_kernel<<<1024, 64>>>(embed);
    argmin_mma<<<1024, 256>>>(in, out);
    fb_kernel<<<296, 256>>>(in, embed, out);
    quant_kernel<<<512, 256>>>(in, embed, out);
    scalar_kernel<<<1, 1024>>>(ecs, out);
    ema_kernel<<<128, 512>>>(emw, out);
}

// round 9
// speedup vs baseline: 2.1063x; 1.4349x over previous
#include <cuda_runtime.h>
#include <cuda_fp16.h>
#include <math.h>
#include <stdint.h>

#define N_PIX   131072
#define TAU     0.002f

// Output layout offsets (flattened tuple, float32) — total 8651778
#define QUANT_OFF 0
#define LOSS_OFF  8388608
#define PERP_OFF  8388609
#define IDX_OFF   8388610
#define NCS_OFF   8519682
#define NEMA_OFF  8520706
#define NEMB_OFF  8586242

// Scratch (device globals; no allocation allowed)
__device__ int   g_idx[N_PIX];
__device__ float g_esqh[1024];                       // -0.5*||e||^2
__device__ float g_counts[1024];
__device__ float g_dwp[8 * 65536];                   // 8-way privatized dw
__device__ float g_scl[1024];
__device__ float g_loss;
// packed split-fp16 codebook: [chunk 16][split 2][kstep 4][n 64][j 8] half2
__device__ __align__(128) __half g_Bpk[16 * 8192];
__device__ int   g_fb_list[N_PIX];
__device__ int   g_fb_count;
__device__ int   g_fb_take;

// ---------------------------------------------------------------------------
// helpers (base PTX only)
// ---------------------------------------------------------------------------
__device__ __forceinline__ uint32_t smem_u32(const void* p) {
    uint32_t a;
    asm("{ .reg .u64 t; cvta.to.shared.u64 t, %1; cvt.u32.u64 %0, t; }" : "=r"(a) : "l"(p));
    return a;
}
__device__ __forceinline__ void mma16(float& d0, float& d1, float& d2, float& d3,
                                      const uint32_t* a, uint32_t b0, uint32_t b1) {
    asm volatile(
        "mma.sync.aligned.m16n8k16.row.col.f32.f16.f16.f32 "
        "{%0,%1,%2,%3}, {%4,%5,%6,%7}, {%8,%9}, {%0,%1,%2,%3};"
        : "+f"(d0), "+f"(d1), "+f"(d2), "+f"(d3)
        : "r"(a[0]), "r"(a[1]), "r"(a[2]), "r"(a[3]), "r"(b0), "r"(b1));
}
#define CP_ASYNC16(dst, src) \
    asm volatile("cp.async.cg.shared.global [%0], [%1], 16;" :: "r"(dst), "l"(src) : "memory")
#define CP_COMMIT() asm volatile("cp.async.commit_group;" ::: "memory")
#define CP_WAIT1()  asm volatile("cp.async.wait_group 1;" ::: "memory")
#define CP_WAIT0()  asm volatile("cp.async.wait_group 0;" ::: "memory")

__device__ __forceinline__ void red_v4(float* p, float a, float b, float c, float d) {
    asm volatile("red.global.add.v4.f32 [%0], {%1,%2,%3,%4};"
                 :: "l"(p), "f"(a), "f"(b), "f"(c), "f"(d) : "memory");
}

__device__ __forceinline__ uint32_t packsplit(float x0, float x1, uint32_t& lo) {
    __half h0 = __float2half_rn(x0), h1 = __float2half_rn(x1);
    __half l0 = __float2half_rn(x0 - __half2float(h0));
    __half l1 = __float2half_rn(x1 - __half2float(h1));
    __half2 hh = __halves2half2(h0, h1), ll = __halves2half2(l0, l1);
    lo = *(uint32_t*)&ll;
    return *(uint32_t*)&hh;
}
// best-2 running update (strict > keeps lowest index; codes ascend)
__device__ __forceinline__ void upd(float& b1, int& i1, float& b2, float s, int idx) {
    if (s > b1) { b2 = b1; b1 = s; i1 = idx; }
    else if (s > b2) { b2 = s; }
}

// ---------------------------------------------------------------------------
// Kernel 1: prep — split-fp16 packed codebook, esqh, zero accumulators
// grid 1024 (code k), 64 threads (channel d)
// ---------------------------------------------------------------------------
__global__ void prep_kernel(const float* __restrict__ embed) {
    int k = blockIdx.x;
    int t = threadIdx.x;
    float v = embed[k * 64 + t];
    #pragma unroll
    for (int i = 0; i < 8; i++) g_dwp[i * 65536 + k * 64 + t] = 0.0f;

    __half hi = __float2half_rn(v);
    __half lo = __float2half_rn(v - __half2float(hi));
    // pack layout: halves index = chunk*8192 + ((split*4+s)*64+n)*16 + j*2 + h
    // pair p covers k_local = 16s + 2p..+1 ; j order {0,4,1,5,2,6,3,7}
    int c = k >> 6, n = k & 63, s = t >> 4, dl = t & 15, p = dl >> 1, h = dl & 1;
    int j = ((p & 3) << 1) | (p >> 2);
    int base = c * 8192;
    g_Bpk[base + (s * 64 + n) * 16 + j * 2 + h] = hi;
    g_Bpk[base + ((4 + s) * 64 + n) * 16 + j * 2 + h] = lo;

    float sq = v * v;
    #pragma unroll
    for (int o = 16; o; o >>= 1) sq += __shfl_down_sync(0xffffffffu, sq, o);
    __shared__ float sm[2];
    if ((t & 31) == 0) sm[t >> 5] = sq;
    __syncthreads();
    if (t == 0) {
        g_esqh[k] = -0.5f * (sm[0] + sm[1]);
        g_counts[k] = 0.0f;
        if (k == 0) { g_loss = 0.0f; g_fb_count = 0; g_fb_take = 0; }
    }
}

// ---------------------------------------------------------------------------
// Kernel 2: split-FP16 argmin via mma.sync m16n8k16 (register accumulators).
// 1024 blocks x 256 threads (8 warps). Block = 128 pixels; warp = 16 pixels.
// Codes in 16 chunks of 64, double-buffered cp.async. Static smem 36KB.
// Tracks s = x.e - 0.5*||e||^2 ; argmin dist == argmax s.
// ---------------------------------------------------------------------------
__global__ void __launch_bounds__(256) argmin_mma(const float* __restrict__ in,
                                                  float* __restrict__ out) {
    __shared__ __align__(16) __half Bsm[16384];   // 2 bufs x 16KB
    __shared__ float esqs[1024];
    uint32_t smb = smem_u32(Bsm);

    const int tid = threadIdx.x;
    const int w   = tid >> 5;
    const int ln  = tid & 31;
    const int g   = ln >> 2;
    const int t   = ln & 3;
    const int p0  = blockIdx.x * 128;
    const int bimg = p0 >> 12;
    const int hw0  = p0 & 4095;

    // chunk 0 -> buf 0
    #pragma unroll
    for (int jj = 0; jj < 4; jj++) {
        int idx = tid + jj * 256;
        CP_ASYNC16(smb + idx * 16, (const char*)g_Bpk + idx * 16);
    }
    CP_COMMIT();

    #pragma unroll
    for (int i = 0; i < 4; i++) esqs[tid + i * 256] = g_esqh[tid + i * 256];

    // A fragments: 16 pixels x 64 ch, split fp16, in registers
    uint32_t ah[4][4], al[4][4];
    {
        const float* ap = in + (size_t)bimg * 262144 + hw0 + w * 16 + g;
        #pragma unroll
        for (int s = 0; s < 4; s++) {
            int d0 = 16 * s + 2 * t;
            ah[s][0] = packsplit(ap[d0 * 4096],          ap[(d0 + 1) * 4096],     al[s][0]); // row g
            ah[s][1] = packsplit(ap[d0 * 4096 + 8],      ap[(d0 + 1) * 4096 + 8], al[s][1]); // row g+8
            ah[s][2] = packsplit(ap[(d0 + 8) * 4096],    ap[(d0 + 9) * 4096],     al[s][2]);
            ah[s][3] = packsplit(ap[(d0 + 8) * 4096 + 8],ap[(d0 + 9) * 4096 + 8], al[s][3]);
        }
    }

    float b1a = -3.4e38f, b2a = -3.4e38f; int i1a = 0;   // pixel row g
    float b1b = -3.4e38f, b2b = -3.4e38f; int i1b = 0;   // pixel row g+8

    for (int c = 0; c < 16; c++) {
        const int buf = c & 1;
        if (c < 15) {
            int nb = (c + 1) & 1;
            #pragma unroll
            for (int jj = 0; jj < 4; jj++) {
                int idx = tid + jj * 256;
                CP_ASYNC16(smb + nb * 16384 + idx * 16,
                           (const char*)g_Bpk + (c + 1) * 16384 + idx * 16);
            }
            CP_COMMIT();
            CP_WAIT1();
        } else {
            CP_WAIT0();
        }
        __syncthreads();

        const uint32_t bb = smb + buf * 16384;
        const int kbase = c * 64;

        #pragma unroll
        for (int nt = 0; nt < 8; nt++) {
            float c0 = 0.f, c1 = 0.f, c2 = 0.f, c3 = 0.f;
            const int nb_ = nt * 8 + g;
            #pragma unroll
            for (int s = 0; s < 4; s++) {
                uint32_t offh = bb + (s * 64 + nb_) * 32 + 8 * t;
                uint32_t offl = offh + 8192;             // split=1 half of chunk
                uint32_t bh0, bh1, bl0, bl1;
                asm volatile("ld.shared.v2.b32 {%0,%1}, [%2];" : "=r"(bh0), "=r"(bh1) : "r"(offh));
                asm volatile("ld.shared.v2.b32 {%0,%1}, [%2];" : "=r"(bl0), "=r"(bl1) : "r"(offl));
                mma16(c0, c1, c2, c3, ah[s], bh0, bh1);
                mma16(c0, c1, c2, c3, al[s], bh0, bh1);
                mma16(c0, c1, c2, c3, ah[s], bl0, bl1);
            }
            int code0 = kbase + nt * 8 + 2 * t;
            float e0 = esqs[code0], e1 = esqs[code0 + 1];
            upd(b1a, i1a, b2a, c0 + e0, code0);
            upd(b1a, i1a, b2a, c1 + e1, code0 + 1);
            upd(b1b, i1b, b2b, c2 + e0, code0);
            upd(b1b, i1b, b2b, c3 + e1, code0 + 1);
        }
        __syncthreads();
    }

    // reduce across the 4 lanes of the group (t = 0..3)
    #pragma unroll
    for (int o = 1; o <= 2; o <<= 1) {
        float ob1 = __shfl_xor_sync(0xffffffffu, b1a, o);
        float ob2 = __shfl_xor_sync(0xffffffffu, b2a, o);
        int   oi1 = __shfl_xor_sync(0xffffffffu, i1a, o);
        if (ob1 > b1a || (ob1 == b1a && oi1 < i1a)) { b2a = fmaxf(b1a, ob2); b1a = ob1; i1a = oi1; }
        else { b2a = fmaxf(b2a, ob1); }
        ob1 = __shfl_xor_sync(0xffffffffu, b1b, o);
        ob2 = __shfl_xor_sync(0xffffffffu, b2b, o);
        oi1 = __shfl_xor_sync(0xffffffffu, i1b, o);
        if (ob1 > b1b || (ob1 == b1b && oi1 < i1b)) { b2b = fmaxf(b1b, ob2); b1b = ob1; i1b = oi1; }
        else { b2b = fmaxf(b2b, ob1); }
    }

    if (t == 0) {
        int n = p0 + w * 16 + g;
        g_idx[n] = i1a;
        out[IDX_OFF + n] = (float)i1a;
        if (b1a - b2a < TAU) g_fb_list[atomicAdd(&g_fb_count, 1)] = n;
        int n2 = n + 8;
        g_idx[n2] = i1b;
        out[IDX_OFF + n2] = (float)i1b;
        if (b1b - b2b < TAU) g_fb_list[atomicAdd(&g_fb_count, 1)] = n2;
    }
}

// ---------------------------------------------------------------------------
// Kernel 2b: exact fp32 fallback for ambiguous pixels
// ---------------------------------------------------------------------------
__global__ void fb_kernel(const float* __restrict__ in,
                          const float* __restrict__ embed,
                          float* __restrict__ out) {
    __shared__ float xs[64];
    __shared__ float rv[256];
    __shared__ int   ri[256];
    __shared__ int   cur;
    while (true) {
        if (threadIdx.x == 0) cur = atomicAdd(&g_fb_take, 1);
        __syncthreads();
        int i = cur;
        if (i >= g_fb_count) break;
        int n = g_fb_list[i];
        int b = n >> 12, hw = n & 4095;
        if (threadIdx.x < 64)
            xs[threadIdx.x] = in[(size_t)b * 262144 + threadIdx.x * 4096 + hw];
        __syncthreads();

        int k0 = threadIdx.x * 4;
        float bv = -3.4e38f; int bi = 0;
        for (int k = k0; k < k0 + 4; k++) {
            const float* e = embed + k * 64;
            float s = g_esqh[k];
            #pragma unroll
            for (int c = 0; c < 64; c++) s = fmaf(xs[c], e[c], s);
            if (s > bv) { bv = s; bi = k; }
        }
        rv[threadIdx.x] = bv; ri[threadIdx.x] = bi;
        __syncthreads();
        for (int o = 128; o; o >>= 1) {
            if (threadIdx.x < o) {
                float v2 = rv[threadIdx.x + o]; int i2 = ri[threadIdx.x + o];
                if (v2 > rv[threadIdx.x] || (v2 == rv[threadIdx.x] && i2 < ri[threadIdx.x])) {
                    rv[threadIdx.x] = v2; ri[threadIdx.x] = i2;
                }
            }
            __syncthreads();
        }
        if (threadIdx.x == 0) { g_idx[n] = ri[0]; out[IDX_OFF + n] = (float)ri[0]; }
        __syncthreads();
    }
}

// ---------------------------------------------------------------------------
// Kernel 3: quantize — one thread per pixel; contiguous embed-row gather,
// coalesced channel-strided in/out, privatized v4 vector reductions for dw.
// ---------------------------------------------------------------------------
__global__ void quant_kernel(const float* __restrict__ in,
                             const float* __restrict__ embed,
                             float* __restrict__ out) {
    int n = blockIdx.x * 256 + threadIdx.x;       // pixel 0..131071
    int b = n >> 12, hw = n & 4095;
    int r = g_idx[n];

    const float4* er = (const float4*)(embed + r * 64);
    const float* ib = in + (size_t)b * 262144 + hw;
    float* ob = out + QUANT_OFF + (size_t)b * 262144 + hw;
    float* dwr = g_dwp + (blockIdx.x & 7) * 65536 + r * 64;

    float s = 0.0f;
    #pragma unroll
    for (int j = 0; j < 16; j++) {
        float4 q = __ldg(er + j);
        int d = j * 4;
        float x0 = ib[(size_t)d * 4096];
        float x1 = ib[(size_t)(d + 1) * 4096];
        float x2 = ib[(size_t)(d + 2) * 4096];
        float x3 = ib[(size_t)(d + 3) * 4096];
        ob[(size_t)d * 4096]       = q.x;
        ob[(size_t)(d + 1) * 4096] = q.y;
        ob[(size_t)(d + 2) * 4096] = q.z;
        ob[(size_t)(d + 3) * 4096] = q.w;
        float e0 = q.x - x0, e1 = q.y - x1, e2 = q.z - x2, e3 = q.w - x3;
        s += e0 * e0 + e1 * e1 + e2 * e2 + e3 * e3;
        red_v4(dwr + d, x0, x1, x2, x3);
    }
    atomicAdd(&g_counts[r], 1.0f);

    #pragma unroll
    for (int o = 16; o; o >>= 1) s += __shfl_down_sync(0xffffffffu, s, o);
    __shared__ float sm[8];
    if ((threadIdx.x & 31) == 0) sm[threadIdx.x >> 5] = s;
    __syncthreads();
    if (threadIdx.x == 0) {
        float tot = 0.0f;
        #pragma unroll
        for (int i = 0; i < 8; i++) tot += sm[i];
        atomicAdd(&g_loss, tot);
    }
}

// ---------------------------------------------------------------------------
// Kernel 4a: scalars
// ---------------------------------------------------------------------------
__global__ void scalar_kernel(const float* __restrict__ ema_cs, float* __restrict__ out) {
    __shared__ float s1[1024];
    __shared__ float s2[1024];
    int k = threadIdx.x;
    float cnt = g_counts[k];
    float ncs = 0.99f * ema_cs[k] + 0.01f * cnt;
    out[NCS_OFF + k] = ncs;
    float p = cnt * (1.0f / 131072.0f);
    s1[k] = ncs;
    s2[k] = p * logf(p + 1e-10f);
    __syncthreads();
    for (int o = 512; o; o >>= 1) {
        if (k < o) { s1[k] += s1[k + o]; s2[k] += s2[k + o]; }
        __syncthreads();
    }
    float nsum = s1[0];
    float csz = (ncs + 1e-5f) / (nsum + 1024.0f * 1e-5f) * nsum;
    g_scl[k] = fmaxf(csz, 1e-5f);
    if (k == 0) {
        out[LOSS_OFF] = 0.25f * g_loss * (1.0f / 8388608.0f);
        out[PERP_OFF] = expf(-s2[0]);
    }
}

// ---------------------------------------------------------------------------
// Kernel 4b: wide EMA update (sums the 8 dw replicas)
// ---------------------------------------------------------------------------
__global__ void ema_kernel(const float* __restrict__ ema_w, float* __restrict__ out) {
    int e = blockIdx.x * 512 + threadIdx.x;       // 0..65535
    int kk = e >> 6;
    float dw = 0.0f;
    #pragma unroll
    for (int i = 0; i < 8; i++) dw += g_dwp[i * 65536 + e];
    float w = 0.99f * ema_w[e] + 0.01f * dw;
    out[NEMA_OFF + e] = w;
    out[NEMB_OFF + e] = w / g_scl[kk];
}

// ---------------------------------------------------------------------------
extern "C" void kernel_launch(void* const* d_in, const int* in_sizes, int n_in,
                              void* d_out, int out_size) {
    const float* in    = (const float*)d_in[0];
    const float* embed = (const float*)d_in[1];
    const float* ecs   = (const float*)d_in[2];
    const float* emw   = (const float*)d_in[3];
    float* out = (float*)d_out;

    prep_kernel<<<1024, 64>>>(embed);
    argmin_mma<<<1024, 256>>>(in, out);
    fb_kernel<<<296, 256>>>(in, embed, out);
    quant_kernel<<<512, 256>>>(in, embed, out);
    scalar_kernel<<<1, 1024>>>(ecs, out);
    ema_kernel<<<128, 512>>>(emw, out);
}